// round 1
// baseline (speedup 1.0000x reference)
#include <cuda_runtime.h>
#include <cuda_bf16.h>

#define N_NODES 100000
#define N_EDGES 800000
#define D 128

// Scratch (device globals — allocation-free rule)
__device__ float g_agg[3][N_NODES][D];   // summed messages per layer
__device__ float g_h[3][N_NODES][D];     // layer-1 activations
__device__ float g_out[3][N_NODES][D];   // layer-2 per-graph outputs
__device__ float g_deg[3][N_NODES];      // in-degree (same for both layers)
__device__ int   g_is64;                 // edge_index dtype flag

// ---------------------------------------------------------------------------
// Detect whether edge_index is int64 or int32.
// Values are in [0, 100000) so for int64 (little-endian) every odd 32-bit word
// is 0. For int32 the odd words are random edge ids (all-zero prob ~1e-320).
// ---------------------------------------------------------------------------
__global__ void detect_idx_kernel(const int* __restrict__ ei_words) {
    if (threadIdx.x == 0 && blockIdx.x == 0) {
        int bad = 0;
        #pragma unroll
        for (int i = 0; i < 64; ++i) bad |= ei_words[2 * i + 1];
        g_is64 = (bad == 0) ? 1 : 0;
    }
}

// ---------------------------------------------------------------------------
// Scatter-add: one warp per edge. Lanes cover 128 floats as float4 each.
// agg[g][dst][:] += X[g][src][:];  deg[g][dst] += 1 (first layer only).
// ---------------------------------------------------------------------------
__global__ void scatter_kernel(const float* __restrict__ X,
                               const void*  __restrict__ ei_raw,
                               float* __restrict__ agg,
                               float* __restrict__ deg,
                               int with_deg) {
    long long widx = (long long)blockIdx.x * (blockDim.x >> 5) + (threadIdx.x >> 5);
    int lane = threadIdx.x & 31;
    const long long total = 3LL * N_EDGES;
    if (widx >= total) return;

    int g = (int)(widx / N_EDGES);
    int e = (int)(widx % N_EDGES);

    long long src, dst;
    if (g_is64) {
        const long long* ei = (const long long*)ei_raw;
        long long base = (long long)g * 2 * N_EDGES;
        src = ei[base + e];
        dst = ei[base + N_EDGES + e];
    } else {
        const int* ei = (const int*)ei_raw;
        long long base = (long long)g * 2 * N_EDGES;
        src = ei[base + e];
        dst = ei[base + N_EDGES + e];
    }

    const float4* xs = (const float4*)(X + ((long long)g * N_NODES + src) * D);
    float4 v = xs[lane];

    float4* ad = (float4*)(agg + ((long long)g * N_NODES + dst) * D);
    atomicAdd(ad + lane, v);   // sm_90+ vector atomic

    if (with_deg && lane == 0)
        atomicAdd(&deg[(long long)g * N_NODES + dst], 1.0f);
}

// ---------------------------------------------------------------------------
// Fused SAGEConv: Out[row] = act( (agg[row]/max(deg,1)) @ Wl + X[row] @ Wr + b )
// Implemented as [agg_n | x] (K=256) @ [Wl ; Wr] (256x128), W in shared memory.
// Block: 512 threads (16 warps). Each warp: 8 rows; each lane: 4 consecutive
// output columns (c = lane*4..lane*4+3). A-values broadcast via shfl.
// ---------------------------------------------------------------------------
__global__ void __launch_bounds__(512, 1)
conv_kernel(const float* __restrict__ Xin,   // [3][N][D]
            const float* __restrict__ Agg,   // [3][N][D]
            const float* __restrict__ Deg,   // [3][N]
            const float* __restrict__ Wl,    // [3][D][D]
            const float* __restrict__ Wr,    // [3][D][D]
            const float* __restrict__ bl,    // [3][D]
            float* __restrict__ Out,         // [3][N][D]
            int relu) {
    extern __shared__ float sW[];            // [256][128] = [Wl ; Wr]
    const int g = blockIdx.y;

    // Load weights into shared memory (vectorized)
    {
        float4* s4 = (float4*)sW;
        const float4* wl4 = (const float4*)(Wl + (long long)g * D * D);
        const float4* wr4 = (const float4*)(Wr + (long long)g * D * D);
        for (int i = threadIdx.x; i < D * D / 4; i += 512) {
            s4[i] = wl4[i];
            s4[D * D / 4 + i] = wr4[i];
        }
    }
    __syncthreads();

    const int warp = threadIdx.x >> 5;
    const int lane = threadIdx.x & 31;
    const int row0 = blockIdx.x * 128 + warp * 8;

    const float* xg = Xin + (long long)g * N_NODES * D;
    const float* ag = Agg + (long long)g * N_NODES * D;
    const float* dg = Deg + (long long)g * N_NODES;

    float4 bias = ((const float4*)(bl + (long long)g * D))[lane];

    // A fragments: a[r][j] = A[row0+r][j*32 + lane], j<4 from agg_norm, j>=4 from x
    float a[8][8];
    #pragma unroll
    for (int r = 0; r < 8; ++r) {
        int row = row0 + r;
        if (row < N_NODES) {
            float dinv = 1.0f / fmaxf(dg[row], 1.0f);
            #pragma unroll
            for (int j = 0; j < 4; ++j)
                a[r][j] = ag[(long long)row * D + j * 32 + lane] * dinv;
            #pragma unroll
            for (int j = 0; j < 4; ++j)
                a[r][4 + j] = xg[(long long)row * D + j * 32 + lane];
        } else {
            #pragma unroll
            for (int j = 0; j < 8; ++j) a[r][j] = 0.0f;
        }
    }

    float4 acc[8];
    #pragma unroll
    for (int r = 0; r < 8; ++r) acc[r] = make_float4(0.f, 0.f, 0.f, 0.f);

    const float4* sW4 = (const float4*)sW;   // [256][32] float4 view

    #pragma unroll
    for (int j = 0; j < 8; ++j) {
        #pragma unroll 4
        for (int kk = 0; kk < 32; ++kk) {
            float4 w = sW4[(j * 32 + kk) * 32 + lane];
            #pragma unroll
            for (int r = 0; r < 8; ++r) {
                float av = __shfl_sync(0xffffffffu, a[r][j], kk);
                acc[r].x = fmaf(av, w.x, acc[r].x);
                acc[r].y = fmaf(av, w.y, acc[r].y);
                acc[r].z = fmaf(av, w.z, acc[r].z);
                acc[r].w = fmaf(av, w.w, acc[r].w);
            }
        }
    }

    float* og = Out + (long long)g * N_NODES * D;
    #pragma unroll
    for (int r = 0; r < 8; ++r) {
        int row = row0 + r;
        if (row >= N_NODES) continue;
        float4 o;
        o.x = acc[r].x + bias.x;
        o.y = acc[r].y + bias.y;
        o.z = acc[r].z + bias.z;
        o.w = acc[r].w + bias.w;
        if (relu) {
            o.x = fmaxf(o.x, 0.f);
            o.y = fmaxf(o.y, 0.f);
            o.z = fmaxf(o.z, 0.f);
            o.w = fmaxf(o.w, 0.f);
        }
        ((float4*)(og + (long long)row * D))[lane] = o;
    }
}

// out = O[0] + 0.5*(O[1] + O[2])
__global__ void combine_kernel(const float* __restrict__ O, float* __restrict__ out) {
    long long i = (long long)blockIdx.x * blockDim.x + threadIdx.x;
    const long long nv = (long long)N_NODES * D / 4;
    if (i >= nv) return;
    float4 x0 = ((const float4*)O)[i];
    float4 x1 = ((const float4*)(O + (long long)N_NODES * D))[i];
    float4 x2 = ((const float4*)(O + 2LL * N_NODES * D))[i];
    float4 o;
    o.x = x0.x + 0.5f * (x1.x + x2.x);
    o.y = x0.y + 0.5f * (x1.y + x2.y);
    o.z = x0.z + 0.5f * (x1.z + x2.z);
    o.w = x0.w + 0.5f * (x1.w + x2.w);
    ((float4*)out)[i] = o;
}

extern "C" void kernel_launch(void* const* d_in, const int* in_sizes, int n_in,
                              void* d_out, int out_size) {
    const float* x   = (const float*)d_in[0];
    const void*  ei  = d_in[1];
    const float* Wl1 = (const float*)d_in[2];
    const float* bl1 = (const float*)d_in[3];
    const float* Wr1 = (const float*)d_in[4];
    const float* Wl2 = (const float*)d_in[5];
    const float* bl2 = (const float*)d_in[6];
    const float* Wr2 = (const float*)d_in[7];

    void *agg_p, *h_p, *out_p, *deg_p;
    cudaGetSymbolAddress(&agg_p, g_agg);
    cudaGetSymbolAddress(&h_p,   g_h);
    cudaGetSymbolAddress(&out_p, g_out);
    cudaGetSymbolAddress(&deg_p, g_deg);
    float* agg = (float*)agg_p;
    float* h   = (float*)h_p;
    float* ob  = (float*)out_p;
    float* deg = (float*)deg_p;

    cudaFuncSetAttribute(conv_kernel, cudaFuncAttributeMaxDynamicSharedMemorySize,
                         256 * 128 * sizeof(float));

    // 0) dtype detect
    detect_idx_kernel<<<1, 32>>>((const int*)ei);

    // 1) zero scratch
    cudaMemsetAsync(agg_p, 0, sizeof(g_agg));
    cudaMemsetAsync(deg_p, 0, sizeof(g_deg));

    // 2) layer-1 aggregation
    const long long total_warps = 3LL * N_EDGES;
    const int sblk = 256;                     // 8 warps/block
    const long long sblocks = (total_warps + 7) / 8;
    scatter_kernel<<<(unsigned)sblocks, sblk>>>(x, ei, agg, deg, 1);

    // 3) layer-1 conv + relu -> h
    dim3 cgrid((N_NODES + 127) / 128, 3);
    conv_kernel<<<cgrid, 512, 256 * 128 * sizeof(float)>>>(
        x, agg, deg, Wl1, Wr1, bl1, h, 1);

    // 4) layer-2 aggregation (same degrees)
    cudaMemsetAsync(agg_p, 0, sizeof(g_agg));
    scatter_kernel<<<(unsigned)sblocks, sblk>>>(h, ei, agg, deg, 0);

    // 5) layer-2 conv -> per-graph out
    conv_kernel<<<cgrid, 512, 256 * 128 * sizeof(float)>>>(
        h, agg, deg, Wl2, Wr2, bl2, ob, 0);

    // 6) combine: out0 + 0.5*(out1+out2)
    const long long nv = (long long)N_NODES * D / 4;
    combine_kernel<<<(unsigned)((nv + 255) / 256), 256>>>(ob, (float*)d_out);
}

// round 2
// speedup vs baseline: 1.5807x; 1.5807x over previous
#include <cuda_runtime.h>
#include <cuda_bf16.h>
#include <cstdint>

#define N_NODES 100000
#define N_EDGES 800000
#define D 128

// Scratch (device globals — allocation-free rule)
__device__ float g_agg[3][N_NODES][D];   // summed messages per layer
__device__ float g_h[3][N_NODES][D];     // layer-1 activations
__device__ float g_out[3][N_NODES][D];   // layer-2 per-graph outputs
__device__ float g_deg[3][N_NODES];      // in-degree (same for both layers)
__device__ int   g_is64;                 // edge_index dtype flag

// ---------------------------------------------------------------------------
// Detect whether edge_index is int64 or int32 (values < 100000 => odd 32-bit
// words are all zero iff int64).
// ---------------------------------------------------------------------------
__global__ void detect_idx_kernel(const int* __restrict__ ei_words) {
    if (threadIdx.x == 0 && blockIdx.x == 0) {
        int bad = 0;
        #pragma unroll
        for (int i = 0; i < 64; ++i) bad |= ei_words[2 * i + 1];
        g_is64 = (bad == 0) ? 1 : 0;
    }
}

// ---------------------------------------------------------------------------
// Scatter-add: one warp per edge; float4 vector atomics.
// ---------------------------------------------------------------------------
__global__ void scatter_kernel(const float* __restrict__ X,
                               const void*  __restrict__ ei_raw,
                               float* __restrict__ agg,
                               float* __restrict__ deg,
                               int with_deg) {
    long long widx = (long long)blockIdx.x * (blockDim.x >> 5) + (threadIdx.x >> 5);
    int lane = threadIdx.x & 31;
    const long long total = 3LL * N_EDGES;
    if (widx >= total) return;

    int g = (int)(widx / N_EDGES);
    int e = (int)(widx % N_EDGES);

    long long src, dst;
    if (g_is64) {
        const long long* ei = (const long long*)ei_raw;
        long long base = (long long)g * 2 * N_EDGES;
        src = ei[base + e];
        dst = ei[base + N_EDGES + e];
    } else {
        const int* ei = (const int*)ei_raw;
        long long base = (long long)g * 2 * N_EDGES;
        src = ei[base + e];
        dst = ei[base + N_EDGES + e];
    }

    const float4* xs = (const float4*)(X + ((long long)g * N_NODES + src) * D);
    float4 v = xs[lane];

    float4* ad = (float4*)(agg + ((long long)g * N_NODES + dst) * D);
    atomicAdd(ad + lane, v);

    if (with_deg && lane == 0)
        atomicAdd(&deg[(long long)g * N_NODES + dst], 1.0f);
}

// ---------------------------------------------------------------------------
// tf32 tensor-core SAGEConv:
//   Out[row] = act( (agg[row]/max(deg,1)) @ Wl + X[row] @ Wr + b )
// as A(128-row tile x K=256) @ W(256x128) via mma.sync.m16n8k8 tf32.
// Block: 256 threads (8 warps); each warp owns 16 rows x 128 cols.
// K chunked by 32; A and W chunks staged in smem as tf32 bit patterns.
// ---------------------------------------------------------------------------
__device__ __forceinline__ unsigned f2tf32(float x) {
    unsigned r;
    asm("cvt.rna.tf32.f32 %0, %1;" : "=r"(r) : "f"(x));
    return r;
}

__global__ void __launch_bounds__(256, 2)
conv_tf32_kernel(const float* __restrict__ Xin,   // [3][N][D]
                 const float* __restrict__ Agg,   // [3][N][D]
                 const float* __restrict__ Deg,   // [3][N]
                 const float* __restrict__ Wl,    // [3][D][D]
                 const float* __restrict__ Wr,    // [3][D][D]
                 const float* __restrict__ bl,    // [3][D]
                 float* __restrict__ Out,         // [3][N][D]
                 int relu) {
    __shared__ unsigned As[128][36];   // A tile chunk, stride 36 (conflict-free frags)
    __shared__ unsigned Ws[32][136];   // W chunk, stride 136 (conflict-free frags)

    const int g    = blockIdx.y;
    const int tid  = threadIdx.x;
    const int warp = tid >> 5;
    const int lane = tid & 31;
    const int rowBase = blockIdx.x * 128;

    const float* xg  = Xin + (size_t)g * N_NODES * D;
    const float* ag  = Agg + (size_t)g * N_NODES * D;
    const float* dg  = Deg + (size_t)g * N_NODES;
    const float* WlG = Wl  + (size_t)g * D * D;
    const float* WrG = Wr  + (size_t)g * D * D;

    float acc[16][4];
    #pragma unroll
    for (int t = 0; t < 16; ++t)
        #pragma unroll
        for (int i = 0; i < 4; ++i) acc[t][i] = 0.0f;

    #pragma unroll 1
    for (int chunk = 0; chunk < 8; ++chunk) {
        const int  kc    = chunk * 32;
        const bool isAgg = (chunk < 4);
        const float* Asrc = isAgg ? (ag + kc) : (xg + (kc - 128));
        const float* Wsrc = isAgg ? (WlG + kc * D) : (WrG + (kc - 128) * D);

        __syncthreads();

        // Stage A chunk: 128 rows x 32 cols (1024 float4, 4/thread)
        #pragma unroll
        for (int i = 0; i < 4; ++i) {
            int idx = tid + i * 256;
            int r   = idx >> 3;          // 0..127
            int kq  = idx & 7;           // 0..7 (float4 index)
            int row = rowBase + r;
            float4 v = make_float4(0.f, 0.f, 0.f, 0.f);
            if (row < N_NODES) {
                v = *(const float4*)(Asrc + (size_t)row * D + kq * 4);
                if (isAgg) {
                    float dinv = 1.0f / fmaxf(dg[row], 1.0f);
                    v.x *= dinv; v.y *= dinv; v.z *= dinv; v.w *= dinv;
                }
            }
            uint4 t;
            t.x = f2tf32(v.x); t.y = f2tf32(v.y);
            t.z = f2tf32(v.z); t.w = f2tf32(v.w);
            *(uint4*)&As[r][kq * 4] = t;
        }

        // Stage W chunk: 32 rows x 128 cols (1024 float4, 4/thread)
        #pragma unroll
        for (int i = 0; i < 4; ++i) {
            int idx = tid + i * 256;
            int k   = idx >> 5;          // 0..31
            int nq  = idx & 31;          // 0..31 (float4 index)
            float4 v = *(const float4*)(Wsrc + k * D + nq * 4);
            uint4 t;
            t.x = f2tf32(v.x); t.y = f2tf32(v.y);
            t.z = f2tf32(v.z); t.w = f2tf32(v.w);
            *(uint4*)&Ws[k][nq * 4] = t;
        }

        __syncthreads();

        // Compute: 4 k-steps of 8 within this chunk
        #pragma unroll
        for (int ks = 0; ks < 4; ++ks) {
            const int k0 = ks * 8;
            const int ar = warp * 16 + (lane >> 2);
            const int ac = k0 + (lane & 3);
            unsigned a0 = As[ar][ac];
            unsigned a1 = As[ar + 8][ac];
            unsigned a2 = As[ar][ac + 4];
            unsigned a3 = As[ar + 8][ac + 4];

            #pragma unroll
            for (int t = 0; t < 16; ++t) {
                const int n0 = t * 8;
                unsigned b0 = Ws[k0 + (lane & 3)][n0 + (lane >> 2)];
                unsigned b1 = Ws[k0 + (lane & 3) + 4][n0 + (lane >> 2)];
                asm volatile(
                    "mma.sync.aligned.m16n8k8.row.col.f32.tf32.tf32.f32 "
                    "{%0,%1,%2,%3}, {%4,%5,%6,%7}, {%8,%9}, {%0,%1,%2,%3};"
                    : "+f"(acc[t][0]), "+f"(acc[t][1]),
                      "+f"(acc[t][2]), "+f"(acc[t][3])
                    : "r"(a0), "r"(a1), "r"(a2), "r"(a3), "r"(b0), "r"(b1));
            }
        }
    }

    // Epilogue: bias + optional relu, float2 stores
    const float* bg = bl + (size_t)g * D;
    float* og = Out + (size_t)g * N_NODES * D;
    const int r0 = rowBase + warp * 16 + (lane >> 2);
    const int r1 = r0 + 8;

    #pragma unroll
    for (int t = 0; t < 16; ++t) {
        const int c = t * 8 + (lane & 3) * 2;
        float2 b = *(const float2*)(bg + c);
        float2 o0 = make_float2(acc[t][0] + b.x, acc[t][1] + b.y);
        float2 o1 = make_float2(acc[t][2] + b.x, acc[t][3] + b.y);
        if (relu) {
            o0.x = fmaxf(o0.x, 0.f); o0.y = fmaxf(o0.y, 0.f);
            o1.x = fmaxf(o1.x, 0.f); o1.y = fmaxf(o1.y, 0.f);
        }
        if (r0 < N_NODES) *(float2*)(og + (size_t)r0 * D + c) = o0;
        if (r1 < N_NODES) *(float2*)(og + (size_t)r1 * D + c) = o1;
    }
}

// out = O[0] + 0.5*(O[1] + O[2])
__global__ void combine_kernel(const float* __restrict__ O, float* __restrict__ out) {
    long long i = (long long)blockIdx.x * blockDim.x + threadIdx.x;
    const long long nv = (long long)N_NODES * D / 4;
    if (i >= nv) return;
    float4 x0 = ((const float4*)O)[i];
    float4 x1 = ((const float4*)(O + (long long)N_NODES * D))[i];
    float4 x2 = ((const float4*)(O + 2LL * N_NODES * D))[i];
    float4 o;
    o.x = x0.x + 0.5f * (x1.x + x2.x);
    o.y = x0.y + 0.5f * (x1.y + x2.y);
    o.z = x0.z + 0.5f * (x1.z + x2.z);
    o.w = x0.w + 0.5f * (x1.w + x2.w);
    ((float4*)out)[i] = o;
}

extern "C" void kernel_launch(void* const* d_in, const int* in_sizes, int n_in,
                              void* d_out, int out_size) {
    const float* x   = (const float*)d_in[0];
    const void*  ei  = d_in[1];
    const float* Wl1 = (const float*)d_in[2];
    const float* bl1 = (const float*)d_in[3];
    const float* Wr1 = (const float*)d_in[4];
    const float* Wl2 = (const float*)d_in[5];
    const float* bl2 = (const float*)d_in[6];
    const float* Wr2 = (const float*)d_in[7];

    void *agg_p, *h_p, *out_p, *deg_p;
    cudaGetSymbolAddress(&agg_p, g_agg);
    cudaGetSymbolAddress(&h_p,   g_h);
    cudaGetSymbolAddress(&out_p, g_out);
    cudaGetSymbolAddress(&deg_p, g_deg);
    float* agg = (float*)agg_p;
    float* h   = (float*)h_p;
    float* ob  = (float*)out_p;
    float* deg = (float*)deg_p;

    // 0) dtype detect
    detect_idx_kernel<<<1, 32>>>((const int*)ei);

    // 1) zero scratch
    cudaMemsetAsync(agg_p, 0, sizeof(g_agg));
    cudaMemsetAsync(deg_p, 0, sizeof(g_deg));

    // 2) layer-1 aggregation
    const long long total_warps = 3LL * N_EDGES;
    const int sblk = 256;                     // 8 warps/block
    const long long sblocks = (total_warps + 7) / 8;
    scatter_kernel<<<(unsigned)sblocks, sblk>>>(x, ei, agg, deg, 1);

    // 3) layer-1 conv + relu -> h
    dim3 cgrid((N_NODES + 127) / 128, 3);
    conv_tf32_kernel<<<cgrid, 256>>>(x, agg, deg, Wl1, Wr1, bl1, h, 1);

    // 4) layer-2 aggregation (same degrees)
    cudaMemsetAsync(agg_p, 0, sizeof(g_agg));
    scatter_kernel<<<(unsigned)sblocks, sblk>>>(h, ei, agg, deg, 0);

    // 5) layer-2 conv -> per-graph out
    conv_tf32_kernel<<<cgrid, 256>>>(h, agg, deg, Wl2, Wr2, bl2, ob, 0);

    // 6) combine: out0 + 0.5*(out1+out2)
    const long long nv = (long long)N_NODES * D / 4;
    combine_kernel<<<(unsigned)((nv + 255) / 256), 256>>>(ob, (float*)d_out);
}

// round 3
// speedup vs baseline: 2.7450x; 1.7366x over previous
#include <cuda_runtime.h>
#include <cuda_bf16.h>
#include <cstdint>

#define N_NODES 100000
#define N_EDGES 800000
#define D 128
#define NTOT (3 * N_NODES)      // 300000 nodes across 3 graphs
#define ETOT (3 * N_EDGES)      // 2.4M edges
#define SCAN_BLK 1024
#define SCAN_NB ((NTOT + SCAN_BLK - 1) / SCAN_BLK)   // 293

// Scratch (device globals — allocation-free rule)
__device__ float g_agg[3][N_NODES][D];   // mean-aggregated messages (normalized)
__device__ float g_h[3][N_NODES][D];     // layer-1 activations
__device__ float g_out[3][N_NODES][D];   // layer-2 per-graph outputs
__device__ int   g_is64;                 // edge_index dtype flag

// CSR scratch
__device__ int g_cnt[NTOT];          // in-degree counts
__device__ int g_rowptr[NTOT + 1];   // CSR row pointers (global across graphs)
__device__ int g_cursor[NTOT];       // fill cursors
__device__ int g_col[ETOT];          // CSR column (src) indices
__device__ int g_bsum[SCAN_NB];      // per-block scan sums

// ---------------------------------------------------------------------------
// int64 vs int32 edge_index detection (values < 100000 => odd words zero iff i64)
// ---------------------------------------------------------------------------
__global__ void detect_idx_kernel(const int* __restrict__ ei_words) {
    if (threadIdx.x == 0 && blockIdx.x == 0) {
        int bad = 0;
        #pragma unroll
        for (int i = 0; i < 64; ++i) bad |= ei_words[2 * i + 1];
        g_is64 = (bad == 0) ? 1 : 0;
    }
}

__device__ __forceinline__ void load_edge(const void* ei_raw, int g, int e,
                                          int& src, int& dst) {
    if (g_is64) {
        const long long* ei = (const long long*)ei_raw;
        long long base = (long long)g * 2 * N_EDGES;
        src = (int)ei[base + e];
        dst = (int)ei[base + N_EDGES + e];
    } else {
        const int* ei = (const int*)ei_raw;
        long long base = (long long)g * 2 * N_EDGES;
        src = ei[base + e];
        dst = ei[base + N_EDGES + e];
    }
}

// ---------------------------------------------------------------------------
// CSR build: count -> scan (3 kernels) -> fill
// ---------------------------------------------------------------------------
__global__ void count_kernel(const void* __restrict__ ei_raw) {
    long long i = (long long)blockIdx.x * blockDim.x + threadIdx.x;
    if (i >= ETOT) return;
    int g = (int)(i / N_EDGES), e = (int)(i % N_EDGES);
    int src, dst;
    load_edge(ei_raw, g, e, src, dst);
    atomicAdd(&g_cnt[g * N_NODES + dst], 1);
}

__global__ void scan1_kernel() {
    __shared__ int s[SCAN_BLK];
    int idx = blockIdx.x * SCAN_BLK + threadIdx.x;
    int v = (idx < NTOT) ? g_cnt[idx] : 0;
    s[threadIdx.x] = v;
    __syncthreads();
    #pragma unroll
    for (int off = 1; off < SCAN_BLK; off <<= 1) {
        int t = (threadIdx.x >= off) ? s[threadIdx.x - off] : 0;
        __syncthreads();
        s[threadIdx.x] += t;
        __syncthreads();
    }
    if (idx < NTOT) g_rowptr[idx] = s[threadIdx.x] - v;   // exclusive, pre-offset
    if (threadIdx.x == SCAN_BLK - 1) g_bsum[blockIdx.x] = s[SCAN_BLK - 1];
}

__global__ void scan2_kernel() {
    __shared__ int s[512];
    int v = (threadIdx.x < SCAN_NB) ? g_bsum[threadIdx.x] : 0;
    s[threadIdx.x] = v;
    __syncthreads();
    #pragma unroll
    for (int off = 1; off < 512; off <<= 1) {
        int t = (threadIdx.x >= off) ? s[threadIdx.x - off] : 0;
        __syncthreads();
        s[threadIdx.x] += t;
        __syncthreads();
    }
    if (threadIdx.x < SCAN_NB) g_bsum[threadIdx.x] = s[threadIdx.x] - v;  // exclusive
}

__global__ void scan3_kernel() {
    int idx = blockIdx.x * SCAN_BLK + threadIdx.x;
    if (idx < NTOT) {
        int r = g_rowptr[idx] + g_bsum[blockIdx.x];
        g_rowptr[idx] = r;
        g_cursor[idx] = r;
    }
    if (idx == 0) g_rowptr[NTOT] = ETOT;
}

__global__ void fill_kernel(const void* __restrict__ ei_raw) {
    long long i = (long long)blockIdx.x * blockDim.x + threadIdx.x;
    if (i >= ETOT) return;
    int g = (int)(i / N_EDGES), e = (int)(i % N_EDGES);
    int src, dst;
    load_edge(ei_raw, g, e, src, dst);
    int pos = atomicAdd(&g_cursor[g * N_NODES + dst], 1);
    g_col[pos] = src;
}

// ---------------------------------------------------------------------------
// Gather aggregation: one warp per dst node; mean over neighbors; no atomics.
//   agg[node][:] = (1/max(deg,1)) * sum_{src in N(node)} X[g][src][:]
// ---------------------------------------------------------------------------
__global__ void __launch_bounds__(256)
gather_kernel(const float* __restrict__ X,    // [3][N][D]
              float* __restrict__ agg) {      // [3][N][D]
    int widx = blockIdx.x * (blockDim.x >> 5) + (threadIdx.x >> 5);
    int lane = threadIdx.x & 31;
    if (widx >= NTOT) return;

    int g = widx / N_NODES;
    const float4* xg = (const float4*)(X + (size_t)g * N_NODES * D);

    int start = g_rowptr[widx];
    int end   = g_rowptr[widx + 1];

    float4 acc = make_float4(0.f, 0.f, 0.f, 0.f);
    for (int p = start; p < end; ++p) {
        int src = g_col[p];                       // uniform per warp -> broadcast
        float4 v = xg[(size_t)src * 32 + lane];
        acc.x += v.x; acc.y += v.y; acc.z += v.z; acc.w += v.w;
    }
    int deg = end - start;
    float norm = 1.0f / (float)max(deg, 1);
    acc.x *= norm; acc.y *= norm; acc.z *= norm; acc.w *= norm;

    ((float4*)agg)[(size_t)widx * 32 + lane] = acc;
}

// ---------------------------------------------------------------------------
// tf32 tensor-core SAGEConv: Out = act( agg_norm @ Wl + X @ Wr + b )
// ---------------------------------------------------------------------------
__device__ __forceinline__ unsigned f2tf32(float x) {
    unsigned r;
    asm("cvt.rna.tf32.f32 %0, %1;" : "=r"(r) : "f"(x));
    return r;
}

__global__ void __launch_bounds__(256, 2)
conv_tf32_kernel(const float* __restrict__ Xin,   // [3][N][D]
                 const float* __restrict__ Agg,   // [3][N][D] (pre-normalized)
                 const float* __restrict__ Wl,    // [3][D][D]
                 const float* __restrict__ Wr,    // [3][D][D]
                 const float* __restrict__ bl,    // [3][D]
                 float* __restrict__ Out,         // [3][N][D]
                 int relu) {
    __shared__ unsigned As[128][36];
    __shared__ unsigned Ws[32][136];

    const int g    = blockIdx.y;
    const int tid  = threadIdx.x;
    const int warp = tid >> 5;
    const int lane = tid & 31;
    const int rowBase = blockIdx.x * 128;

    const float* xg  = Xin + (size_t)g * N_NODES * D;
    const float* ag  = Agg + (size_t)g * N_NODES * D;
    const float* WlG = Wl  + (size_t)g * D * D;
    const float* WrG = Wr  + (size_t)g * D * D;

    float acc[16][4];
    #pragma unroll
    for (int t = 0; t < 16; ++t)
        #pragma unroll
        for (int i = 0; i < 4; ++i) acc[t][i] = 0.0f;

    #pragma unroll 1
    for (int chunk = 0; chunk < 8; ++chunk) {
        const int  kc    = chunk * 32;
        const bool isAgg = (chunk < 4);
        const float* Asrc = isAgg ? (ag + kc) : (xg + (kc - 128));
        const float* Wsrc = isAgg ? (WlG + kc * D) : (WrG + (kc - 128) * D);

        __syncthreads();

        // Stage A chunk: 128 rows x 32 cols
        #pragma unroll
        for (int i = 0; i < 4; ++i) {
            int idx = tid + i * 256;
            int r   = idx >> 3;
            int kq  = idx & 7;
            int row = rowBase + r;
            float4 v = make_float4(0.f, 0.f, 0.f, 0.f);
            if (row < N_NODES)
                v = *(const float4*)(Asrc + (size_t)row * D + kq * 4);
            uint4 t;
            t.x = f2tf32(v.x); t.y = f2tf32(v.y);
            t.z = f2tf32(v.z); t.w = f2tf32(v.w);
            *(uint4*)&As[r][kq * 4] = t;
        }

        // Stage W chunk: 32 rows x 128 cols
        #pragma unroll
        for (int i = 0; i < 4; ++i) {
            int idx = tid + i * 256;
            int k   = idx >> 5;
            int nq  = idx & 31;
            float4 v = *(const float4*)(Wsrc + k * D + nq * 4);
            uint4 t;
            t.x = f2tf32(v.x); t.y = f2tf32(v.y);
            t.z = f2tf32(v.z); t.w = f2tf32(v.w);
            *(uint4*)&Ws[k][nq * 4] = t;
        }

        __syncthreads();

        #pragma unroll
        for (int ks = 0; ks < 4; ++ks) {
            const int k0 = ks * 8;
            const int ar = warp * 16 + (lane >> 2);
            const int ac = k0 + (lane & 3);
            unsigned a0 = As[ar][ac];
            unsigned a1 = As[ar + 8][ac];
            unsigned a2 = As[ar][ac + 4];
            unsigned a3 = As[ar + 8][ac + 4];

            #pragma unroll
            for (int t = 0; t < 16; ++t) {
                const int n0 = t * 8;
                unsigned b0 = Ws[k0 + (lane & 3)][n0 + (lane >> 2)];
                unsigned b1 = Ws[k0 + (lane & 3) + 4][n0 + (lane >> 2)];
                asm volatile(
                    "mma.sync.aligned.m16n8k8.row.col.f32.tf32.tf32.f32 "
                    "{%0,%1,%2,%3}, {%4,%5,%6,%7}, {%8,%9}, {%0,%1,%2,%3};"
                    : "+f"(acc[t][0]), "+f"(acc[t][1]),
                      "+f"(acc[t][2]), "+f"(acc[t][3])
                    : "r"(a0), "r"(a1), "r"(a2), "r"(a3), "r"(b0), "r"(b1));
            }
        }
    }

    const float* bg = bl + (size_t)g * D;
    float* og = Out + (size_t)g * N_NODES * D;
    const int r0 = rowBase + warp * 16 + (lane >> 2);
    const int r1 = r0 + 8;

    #pragma unroll
    for (int t = 0; t < 16; ++t) {
        const int c = t * 8 + (lane & 3) * 2;
        float2 b = *(const float2*)(bg + c);
        float2 o0 = make_float2(acc[t][0] + b.x, acc[t][1] + b.y);
        float2 o1 = make_float2(acc[t][2] + b.x, acc[t][3] + b.y);
        if (relu) {
            o0.x = fmaxf(o0.x, 0.f); o0.y = fmaxf(o0.y, 0.f);
            o1.x = fmaxf(o1.x, 0.f); o1.y = fmaxf(o1.y, 0.f);
        }
        if (r0 < N_NODES) *(float2*)(og + (size_t)r0 * D + c) = o0;
        if (r1 < N_NODES) *(float2*)(og + (size_t)r1 * D + c) = o1;
    }
}

// out = O[0] + 0.5*(O[1] + O[2])
__global__ void combine_kernel(const float* __restrict__ O, float* __restrict__ out) {
    long long i = (long long)blockIdx.x * blockDim.x + threadIdx.x;
    const long long nv = (long long)N_NODES * D / 4;
    if (i >= nv) return;
    float4 x0 = ((const float4*)O)[i];
    float4 x1 = ((const float4*)(O + (long long)N_NODES * D))[i];
    float4 x2 = ((const float4*)(O + 2LL * N_NODES * D))[i];
    float4 o;
    o.x = x0.x + 0.5f * (x1.x + x2.x);
    o.y = x0.y + 0.5f * (x1.y + x2.y);
    o.z = x0.z + 0.5f * (x1.z + x2.z);
    o.w = x0.w + 0.5f * (x1.w + x2.w);
    ((float4*)out)[i] = o;
}

extern "C" void kernel_launch(void* const* d_in, const int* in_sizes, int n_in,
                              void* d_out, int out_size) {
    const float* x   = (const float*)d_in[0];
    const void*  ei  = d_in[1];
    const float* Wl1 = (const float*)d_in[2];
    const float* bl1 = (const float*)d_in[3];
    const float* Wr1 = (const float*)d_in[4];
    const float* Wl2 = (const float*)d_in[5];
    const float* bl2 = (const float*)d_in[6];
    const float* Wr2 = (const float*)d_in[7];

    void *agg_p, *h_p, *out_p, *cnt_p;
    cudaGetSymbolAddress(&agg_p, g_agg);
    cudaGetSymbolAddress(&h_p,   g_h);
    cudaGetSymbolAddress(&out_p, g_out);
    cudaGetSymbolAddress(&cnt_p, g_cnt);
    float* agg = (float*)agg_p;
    float* h   = (float*)h_p;
    float* ob  = (float*)out_p;

    // 0) dtype detect
    detect_idx_kernel<<<1, 32>>>((const int*)ei);

    // 1) CSR build (shared by both layers)
    cudaMemsetAsync(cnt_p, 0, sizeof(g_cnt));
    const int eblk = 256;
    const int egrid = (ETOT + eblk - 1) / eblk;
    count_kernel<<<egrid, eblk>>>(ei);
    scan1_kernel<<<SCAN_NB, SCAN_BLK>>>();
    scan2_kernel<<<1, 512>>>();
    scan3_kernel<<<SCAN_NB, SCAN_BLK>>>();
    fill_kernel<<<egrid, eblk>>>(ei);

    // 2) layer-1 aggregation (gather, normalized)
    const int ggrid = (NTOT * 32 + 255) / 256;   // one warp per node
    gather_kernel<<<ggrid, 256>>>(x, agg);

    // 3) layer-1 conv + relu -> h
    dim3 cgrid((N_NODES + 127) / 128, 3);
    conv_tf32_kernel<<<cgrid, 256>>>(x, agg, Wl1, Wr1, bl1, h, 1);

    // 4) layer-2 aggregation
    gather_kernel<<<ggrid, 256>>>(h, agg);

    // 5) layer-2 conv -> per-graph out
    conv_tf32_kernel<<<cgrid, 256>>>(h, agg, Wl2, Wr2, bl2, ob, 0);

    // 6) combine: out0 + 0.5*(out1+out2)
    const long long nv = (long long)N_NODES * D / 4;
    combine_kernel<<<(unsigned)((nv + 255) / 256), 256>>>(ob, (float*)d_out);
}

// round 4
// speedup vs baseline: 3.1374x; 1.1430x over previous
#include <cuda_runtime.h>
#include <cuda_bf16.h>
#include <cstdint>

#define N_NODES 100000
#define N_EDGES 800000
#define D 128
#define NTOT (3 * N_NODES)
#define ETOT (3 * N_EDGES)
#define SCAN_BLK 1024
#define SCAN_NB ((NTOT + SCAN_BLK - 1) / SCAN_BLK)   // 293

// Scratch (device globals — allocation-free rule)
__device__ float g_agg[3][N_NODES][D];
__device__ float g_h[3][N_NODES][D];
__device__ float g_out[3][N_NODES][D];
__device__ int   g_is64;
__device__ unsigned g_Wtf[2 * 3 * 256 * 128];   // preconverted tf32 [layer][g][256][128]

// CSR scratch
__device__ int g_cnt[NTOT];
__device__ int g_rowptr[NTOT + 1];
__device__ int g_cursor[NTOT];
__device__ int g_col[ETOT];
__device__ int g_bsum[SCAN_NB];

// ---------------------------------------------------------------------------
__global__ void detect_idx_kernel(const int* __restrict__ ei_words) {
    if (threadIdx.x == 0 && blockIdx.x == 0) {
        int bad = 0;
        #pragma unroll
        for (int i = 0; i < 64; ++i) bad |= ei_words[2 * i + 1];
        g_is64 = (bad == 0) ? 1 : 0;
    }
}

__device__ __forceinline__ void load_edge(const void* ei_raw, int g, int e,
                                          int& src, int& dst) {
    if (g_is64) {
        const long long* ei = (const long long*)ei_raw;
        long long base = (long long)g * 2 * N_EDGES;
        src = (int)ei[base + e];
        dst = (int)ei[base + N_EDGES + e];
    } else {
        const int* ei = (const int*)ei_raw;
        long long base = (long long)g * 2 * N_EDGES;
        src = ei[base + e];
        dst = ei[base + N_EDGES + e];
    }
}

// ---------------------------------------------------------------------------
// CSR build: count -> scan -> fill
// ---------------------------------------------------------------------------
__global__ void count_kernel(const void* __restrict__ ei_raw) {
    long long i = (long long)blockIdx.x * blockDim.x + threadIdx.x;
    if (i >= ETOT) return;
    int g = (int)(i / N_EDGES), e = (int)(i % N_EDGES);
    int src, dst;
    load_edge(ei_raw, g, e, src, dst);
    atomicAdd(&g_cnt[g * N_NODES + dst], 1);
}

__global__ void scan1_kernel() {
    __shared__ int s[SCAN_BLK];
    int idx = blockIdx.x * SCAN_BLK + threadIdx.x;
    int v = (idx < NTOT) ? g_cnt[idx] : 0;
    s[threadIdx.x] = v;
    __syncthreads();
    #pragma unroll
    for (int off = 1; off < SCAN_BLK; off <<= 1) {
        int t = (threadIdx.x >= off) ? s[threadIdx.x - off] : 0;
        __syncthreads();
        s[threadIdx.x] += t;
        __syncthreads();
    }
    if (idx < NTOT) g_rowptr[idx] = s[threadIdx.x] - v;
    if (threadIdx.x == SCAN_BLK - 1) g_bsum[blockIdx.x] = s[SCAN_BLK - 1];
}

__global__ void scan2_kernel() {
    __shared__ int s[512];
    int v = (threadIdx.x < SCAN_NB) ? g_bsum[threadIdx.x] : 0;
    s[threadIdx.x] = v;
    __syncthreads();
    #pragma unroll
    for (int off = 1; off < 512; off <<= 1) {
        int t = (threadIdx.x >= off) ? s[threadIdx.x - off] : 0;
        __syncthreads();
        s[threadIdx.x] += t;
        __syncthreads();
    }
    if (threadIdx.x < SCAN_NB) g_bsum[threadIdx.x] = s[threadIdx.x] - v;
}

__global__ void scan3_kernel() {
    int idx = blockIdx.x * SCAN_BLK + threadIdx.x;
    if (idx < NTOT) {
        int r = g_rowptr[idx] + g_bsum[blockIdx.x];
        g_rowptr[idx] = r;
        g_cursor[idx] = r;
    }
    if (idx == 0) g_rowptr[NTOT] = ETOT;
}

__global__ void fill_kernel(const void* __restrict__ ei_raw) {
    long long i = (long long)blockIdx.x * blockDim.x + threadIdx.x;
    if (i >= ETOT) return;
    int g = (int)(i / N_EDGES), e = (int)(i % N_EDGES);
    int src, dst;
    load_edge(ei_raw, g, e, src, dst);
    int pos = atomicAdd(&g_cursor[g * N_NODES + dst], 1);
    g_col[pos] = src;
}

// ---------------------------------------------------------------------------
// Preconvert weights to tf32: g_Wtf[layer][g][256][128], rows 0..127=Wl,
// 128..255=Wr.
// ---------------------------------------------------------------------------
__device__ __forceinline__ unsigned f2tf32(float x) {
    unsigned r;
    asm("cvt.rna.tf32.f32 %0, %1;" : "=r"(r) : "f"(x));
    return r;
}

__global__ void wconv_kernel(const float* __restrict__ Wl1, const float* __restrict__ Wr1,
                             const float* __restrict__ Wl2, const float* __restrict__ Wr2) {
    int i = blockIdx.x * blockDim.x + threadIdx.x;           // < 2*3*256*128
    int l   = i >> 17;               // /131072... careful: 3*256*128 = 98304 per layer
    // recompute properly:
    l = i / 98304;
    int rem = i - l * 98304;
    int g   = rem / 32768;
    int r2  = rem - g * 32768;
    int row = r2 >> 7;
    int col = r2 & 127;
    const float* Wl = l ? Wl2 : Wl1;
    const float* Wr = l ? Wr2 : Wr1;
    float v = (row < 128) ? Wl[(g * 128 + row) * 128 + col]
                          : Wr[(g * 128 + (row - 128)) * 128 + col];
    g_Wtf[i] = f2tf32(v);
}

// ---------------------------------------------------------------------------
// Gather aggregation (CSR, no atomics), 2-way unrolled for MLP.
// ---------------------------------------------------------------------------
__global__ void __launch_bounds__(256)
gather_kernel(const float* __restrict__ X, float* __restrict__ agg) {
    int widx = blockIdx.x * (blockDim.x >> 5) + (threadIdx.x >> 5);
    int lane = threadIdx.x & 31;
    if (widx >= NTOT) return;

    int g = widx / N_NODES;
    const float4* xg = (const float4*)(X + (size_t)g * N_NODES * D);

    int start = g_rowptr[widx];
    int end   = g_rowptr[widx + 1];

    float4 acc0 = make_float4(0.f, 0.f, 0.f, 0.f);
    float4 acc1 = make_float4(0.f, 0.f, 0.f, 0.f);
    int p = start;
    for (; p + 1 < end; p += 2) {
        int s0 = g_col[p], s1 = g_col[p + 1];
        float4 v0 = xg[(size_t)s0 * 32 + lane];
        float4 v1 = xg[(size_t)s1 * 32 + lane];
        acc0.x += v0.x; acc0.y += v0.y; acc0.z += v0.z; acc0.w += v0.w;
        acc1.x += v1.x; acc1.y += v1.y; acc1.z += v1.z; acc1.w += v1.w;
    }
    if (p < end) {
        int s0 = g_col[p];
        float4 v0 = xg[(size_t)s0 * 32 + lane];
        acc0.x += v0.x; acc0.y += v0.y; acc0.z += v0.z; acc0.w += v0.w;
    }
    acc0.x += acc1.x; acc0.y += acc1.y; acc0.z += acc1.z; acc0.w += acc1.w;

    int deg = end - start;
    float norm = 1.0f / (float)max(deg, 1);
    acc0.x *= norm; acc0.y *= norm; acc0.z *= norm; acc0.w *= norm;
    ((float4*)agg)[(size_t)widx * 32 + lane] = acc0;
}

// ---------------------------------------------------------------------------
// cp.async helpers
// ---------------------------------------------------------------------------
__device__ __forceinline__ void cp_async16(uint32_t dst, const void* src, int bytes) {
    asm volatile("cp.async.cg.shared.global [%0], [%1], 16, %2;"
                 :: "r"(dst), "l"(src), "r"(bytes));
}
__device__ __forceinline__ void cp_commit() {
    asm volatile("cp.async.commit_group;");
}
template <int N>
__device__ __forceinline__ void cp_wait() {
    asm volatile("cp.async.wait_group %0;" :: "n"(N));
}

// ---------------------------------------------------------------------------
// Pipelined tf32 SAGEConv: Out = act( agg @ Wl + X @ Wr + b )
// Block 256 thr, tile M=128 N=128, K=256 in 8 chunks of 32, double-buffered
// cp.async. Warps 4x2 -> warp tile m32 x n64.
// Dynamic smem: As[2][128][36] + Ws[2][32][136] floats = 71680 B.
// ---------------------------------------------------------------------------
#define AS_STRIDE 36
#define WS_STRIDE 136
#define AS_BUF (128 * AS_STRIDE)       // 4608 floats
#define WS_BUF (32 * WS_STRIDE)        // 4352 floats
#define SMEM_FLOATS (2 * AS_BUF + 2 * WS_BUF)

__global__ void __launch_bounds__(256, 2)
conv_tf32_kernel(const float* __restrict__ Xin,
                 const float* __restrict__ Agg,
                 const float* __restrict__ bl,
                 float* __restrict__ Out,
                 int layer, int relu) {
    extern __shared__ float smem[];
    float* As = smem;                       // [2][128][36]
    unsigned* Ws = (unsigned*)(smem + 2 * AS_BUF);   // [2][32][136] tf32 bits

    const int g    = blockIdx.y;
    const int tid  = threadIdx.x;
    const int warp = tid >> 5;
    const int lane = tid & 31;
    const int wm   = warp >> 1;             // 0..3
    const int wn   = warp & 1;              // 0..1
    const int rowBase = blockIdx.x * 128;

    const float* xg = Xin + (size_t)g * N_NODES * D;
    const float* ag = Agg + (size_t)g * N_NODES * D;
    const unsigned* Wtf = g_Wtf + (size_t)(layer * 3 + g) * 256 * 128;

    uint32_t As_base = (uint32_t)__cvta_generic_to_shared(As);
    uint32_t Ws_base = (uint32_t)__cvta_generic_to_shared(Ws);

    // Per-thread staging coords
    const int a_r  = tid >> 3;              // row in tile chunk (using idx=tid..)
    const int a_kq = tid & 7;               // float4 col
    const int w_k  = tid >> 5;
    const int w_nq = tid & 31;

    auto stageA = [&](int chunk, int buf) {
        const float* Asrc = (chunk < 4) ? (ag + chunk * 32) : (xg + (chunk - 4) * 32);
        #pragma unroll
        for (int i = 0; i < 4; ++i) {
            int idx = tid + i * 256;
            int r = idx >> 3, kq = idx & 7;
            int row = rowBase + r;
            const float* src = Asrc + (size_t)row * D + kq * 4;
            uint32_t dst = As_base + (uint32_t)((buf * AS_BUF + r * AS_STRIDE + kq * 4) * 4);
            cp_async16(dst, src, (row < N_NODES) ? 16 : 0);
        }
    };
    auto stageW = [&](int chunk, int buf) {
        const unsigned* Wsrc = Wtf + (size_t)(chunk * 32) * 128;
        #pragma unroll
        for (int i = 0; i < 4; ++i) {
            int idx = tid + i * 256;
            int k = idx >> 5, nq = idx & 31;
            uint32_t dst = Ws_base + (uint32_t)((buf * WS_BUF + k * WS_STRIDE + nq * 4) * 4);
            cp_async16(dst, Wsrc + k * 128 + nq * 4, 16);
        }
    };

    float acc[2][8][4];
    #pragma unroll
    for (int mt = 0; mt < 2; ++mt)
        #pragma unroll
        for (int nt = 0; nt < 8; ++nt)
            #pragma unroll
            for (int i = 0; i < 4; ++i) acc[mt][nt][i] = 0.0f;

    stageA(0, 0); stageW(0, 0); cp_commit();

    #pragma unroll 1
    for (int c = 0; c < 8; ++c) {
        int buf = c & 1;
        if (c < 7) {
            stageA(c + 1, buf ^ 1); stageW(c + 1, buf ^ 1); cp_commit();
            cp_wait<1>();
        } else {
            cp_wait<0>();
        }
        __syncthreads();

        const float*    Ab = As + buf * AS_BUF;
        const unsigned* Wb = Ws + buf * WS_BUF;

        #pragma unroll
        for (int ks = 0; ks < 4; ++ks) {
            const int k0 = ks * 8;
            const int ac = k0 + (lane & 3);

            unsigned a[2][4];
            #pragma unroll
            for (int mt = 0; mt < 2; ++mt) {
                int ar = wm * 32 + mt * 16 + (lane >> 2);
                a[mt][0] = f2tf32(Ab[ar * AS_STRIDE + ac]);
                a[mt][1] = f2tf32(Ab[(ar + 8) * AS_STRIDE + ac]);
                a[mt][2] = f2tf32(Ab[ar * AS_STRIDE + ac + 4]);
                a[mt][3] = f2tf32(Ab[(ar + 8) * AS_STRIDE + ac + 4]);
            }

            #pragma unroll
            for (int nt = 0; nt < 8; ++nt) {
                int n0 = wn * 64 + nt * 8 + (lane >> 2);
                unsigned b0 = Wb[(k0 + (lane & 3)) * WS_STRIDE + n0];
                unsigned b1 = Wb[(k0 + (lane & 3) + 4) * WS_STRIDE + n0];
                #pragma unroll
                for (int mt = 0; mt < 2; ++mt) {
                    asm volatile(
                        "mma.sync.aligned.m16n8k8.row.col.f32.tf32.tf32.f32 "
                        "{%0,%1,%2,%3}, {%4,%5,%6,%7}, {%8,%9}, {%0,%1,%2,%3};"
                        : "+f"(acc[mt][nt][0]), "+f"(acc[mt][nt][1]),
                          "+f"(acc[mt][nt][2]), "+f"(acc[mt][nt][3])
                        : "r"(a[mt][0]), "r"(a[mt][1]), "r"(a[mt][2]), "r"(a[mt][3]),
                          "r"(b0), "r"(b1));
                }
            }
        }
        __syncthreads();
    }

    // Epilogue
    const float* bg = bl + (size_t)g * D;
    float* og = Out + (size_t)g * N_NODES * D;

    #pragma unroll
    for (int mt = 0; mt < 2; ++mt) {
        const int r0 = rowBase + wm * 32 + mt * 16 + (lane >> 2);
        const int r1 = r0 + 8;
        #pragma unroll
        for (int nt = 0; nt < 8; ++nt) {
            const int ccol = wn * 64 + nt * 8 + (lane & 3) * 2;
            float2 b = *(const float2*)(bg + ccol);
            float2 o0 = make_float2(acc[mt][nt][0] + b.x, acc[mt][nt][1] + b.y);
            float2 o1 = make_float2(acc[mt][nt][2] + b.x, acc[mt][nt][3] + b.y);
            if (relu) {
                o0.x = fmaxf(o0.x, 0.f); o0.y = fmaxf(o0.y, 0.f);
                o1.x = fmaxf(o1.x, 0.f); o1.y = fmaxf(o1.y, 0.f);
            }
            if (r0 < N_NODES) *(float2*)(og + (size_t)r0 * D + ccol) = o0;
            if (r1 < N_NODES) *(float2*)(og + (size_t)r1 * D + ccol) = o1;
        }
    }
}

// out = O[0] + 0.5*(O[1] + O[2])
__global__ void combine_kernel(const float* __restrict__ O, float* __restrict__ out) {
    long long i = (long long)blockIdx.x * blockDim.x + threadIdx.x;
    const long long nv = (long long)N_NODES * D / 4;
    if (i >= nv) return;
    float4 x0 = ((const float4*)O)[i];
    float4 x1 = ((const float4*)(O + (long long)N_NODES * D))[i];
    float4 x2 = ((const float4*)(O + 2LL * N_NODES * D))[i];
    float4 o;
    o.x = x0.x + 0.5f * (x1.x + x2.x);
    o.y = x0.y + 0.5f * (x1.y + x2.y);
    o.z = x0.z + 0.5f * (x1.z + x2.z);
    o.w = x0.w + 0.5f * (x1.w + x2.w);
    ((float4*)out)[i] = o;
}

extern "C" void kernel_launch(void* const* d_in, const int* in_sizes, int n_in,
                              void* d_out, int out_size) {
    const float* x   = (const float*)d_in[0];
    const void*  ei  = d_in[1];
    const float* Wl1 = (const float*)d_in[2];
    const float* bl1 = (const float*)d_in[3];
    const float* Wr1 = (const float*)d_in[4];
    const float* Wl2 = (const float*)d_in[5];
    const float* bl2 = (const float*)d_in[6];
    const float* Wr2 = (const float*)d_in[7];

    void *agg_p, *h_p, *out_p, *cnt_p;
    cudaGetSymbolAddress(&agg_p, g_agg);
    cudaGetSymbolAddress(&h_p,   g_h);
    cudaGetSymbolAddress(&out_p, g_out);
    cudaGetSymbolAddress(&cnt_p, g_cnt);
    float* agg = (float*)agg_p;
    float* h   = (float*)h_p;
    float* ob  = (float*)out_p;

    cudaFuncSetAttribute(conv_tf32_kernel,
                         cudaFuncAttributeMaxDynamicSharedMemorySize,
                         SMEM_FLOATS * 4);

    // 0) dtype detect + weight preconvert
    detect_idx_kernel<<<1, 32>>>((const int*)ei);
    wconv_kernel<<<(2 * 3 * 256 * 128) / 256, 256>>>(Wl1, Wr1, Wl2, Wr2);

    // 1) CSR build (shared by both layers)
    cudaMemsetAsync(cnt_p, 0, sizeof(g_cnt));
    const int eblk = 256;
    const int egrid = (ETOT + eblk - 1) / eblk;
    count_kernel<<<egrid, eblk>>>(ei);
    scan1_kernel<<<SCAN_NB, SCAN_BLK>>>();
    scan2_kernel<<<1, 512>>>();
    scan3_kernel<<<SCAN_NB, SCAN_BLK>>>();
    fill_kernel<<<egrid, eblk>>>(ei);

    // 2) layer-1 aggregation
    const int ggrid = (NTOT * 32 + 255) / 256;
    gather_kernel<<<ggrid, 256>>>(x, agg);

    // 3) layer-1 conv + relu -> h
    dim3 cgrid((N_NODES + 127) / 128, 3);
    conv_tf32_kernel<<<cgrid, 256, SMEM_FLOATS * 4>>>(x, agg, bl1, h, 0, 1);

    // 4) layer-2 aggregation
    gather_kernel<<<ggrid, 256>>>(h, agg);

    // 5) layer-2 conv -> per-graph out
    conv_tf32_kernel<<<cgrid, 256, SMEM_FLOATS * 4>>>(h, agg, bl2, ob, 1, 0);

    // 6) combine
    const long long nv = (long long)N_NODES * D / 4;
    combine_kernel<<<(unsigned)((nv + 255) / 256), 256>>>(ob, (float*)d_out);
}